// round 15
// baseline (speedup 1.0000x reference)
#include <cuda_runtime.h>
#include <cuda_fp16.h>
#include <cstdint>

#define Bb 4
#define Tt 2048
#define Cc 1024
#define Hh 16
#define Dd 64
#define Kdim 1024
#define NQKV 3072
#define Mrows 8192
#define LOG2E 1.4426950408889634f

// ---------------------------------------------------------------------------
// scratch (__device__ globals; allocation-free). All fp16 (stored as u16).
// g_wta/g_wtp hold NON-transposed fp16 weights [Kdim][N] (K-major rows).
// ---------------------------------------------------------------------------
__device__ uint16_t g_xx[(size_t)Mrows*Kdim];
__device__ uint16_t g_yy[(size_t)Mrows*Kdim];
__device__ uint16_t g_wta[(size_t)Kdim*NQKV];
__device__ uint16_t g_wtp[(size_t)Kdim*Cc];

// attention operands, [b,h,t,d] fp16 (q pre-scaled by 1/8)
__device__ uint16_t g_qq[(size_t)Bb*Hh*Tt*Dd];
__device__ uint16_t g_kk[(size_t)Bb*Hh*Tt*Dd];
__device__ uint16_t g_vv[(size_t)Bb*Hh*Tt*Dd];

// ---------------------------------------------------------------------------
// helpers
// ---------------------------------------------------------------------------
__device__ __forceinline__ uint32_t smem_u32(const void* p) {
    uint32_t a;
    asm("{ .reg .u64 t; cvta.to.shared.u64 t, %1; cvt.u32.u64 %0, t; }" : "=r"(a) : "l"(p));
    return a;
}
__device__ __forceinline__ void cp16(uint32_t dst, const void* src) {
    asm volatile("cp.async.cg.shared.global [%0], [%1], 16;" :: "r"(dst), "l"(src));
}
#define CP_COMMIT() asm volatile("cp.async.commit_group;" ::: "memory")
#define CP_WAIT(n)  asm volatile("cp.async.wait_group %0;" :: "n"(n) : "memory")

__device__ __forceinline__ void mma16816(float d[4], const uint32_t a[4], const uint32_t b[2]) {
    asm volatile(
        "mma.sync.aligned.m16n8k16.row.col.f32.f16.f16.f32 "
        "{%0,%1,%2,%3}, {%4,%5,%6,%7}, {%8,%9}, {%0,%1,%2,%3};"
        : "+f"(d[0]), "+f"(d[1]), "+f"(d[2]), "+f"(d[3])
        : "r"(a[0]), "r"(a[1]), "r"(a[2]), "r"(a[3]), "r"(b[0]), "r"(b[1]));
}
__device__ __forceinline__ void ldsm_x4(uint32_t r[4], uint32_t a) {
    asm volatile("ldmatrix.sync.aligned.m8n8.x4.shared.b16 {%0,%1,%2,%3}, [%4];"
        : "=r"(r[0]), "=r"(r[1]), "=r"(r[2]), "=r"(r[3]) : "r"(a));
}
__device__ __forceinline__ void ldsm_x4_t(uint32_t r[4], uint32_t a) {
    asm volatile("ldmatrix.sync.aligned.m8n8.x4.trans.shared.b16 {%0,%1,%2,%3}, [%4];"
        : "=r"(r[0]), "=r"(r[1]), "=r"(r[2]), "=r"(r[3]) : "r"(a));
}

__device__ __forceinline__ uint16_t to_h(float v) {
    __half hb = __float2half_rn(v);
    return *reinterpret_cast<uint16_t*>(&hb);
}
__device__ __forceinline__ uint32_t pack_h2(float a, float b) {
    __half2 h2 = __floats2half2_rn(a, b);
    return *reinterpret_cast<uint32_t*>(&h2);
}
__device__ __forceinline__ uint32_t h2exp2_u32(uint32_t x) {
    __half2 h = *reinterpret_cast<__half2*>(&x);
    __half2 r = h2exp2(h);
    return *reinterpret_cast<uint32_t*>(&r);
}

// ---------------------------------------------------------------------------
// prep: ONE pure fp32->fp16 convert pass over x, W_attn, W_proj.
// ---------------------------------------------------------------------------
__global__ void prep_kernel(const float* __restrict__ x,
                            const float* __restrict__ Wa,
                            const float* __restrict__ Wp)
{
    const size_t n_x = (size_t)Mrows * Kdim / 4;
    const size_t n_a = (size_t)Kdim * NQKV / 4;
    const size_t n_p = (size_t)Kdim * Cc / 4;
    const size_t tot = n_x + n_a + n_p;
    for (size_t i = blockIdx.x * (size_t)blockDim.x + threadIdx.x; i < tot;
         i += (size_t)gridDim.x * blockDim.x) {
        const float* src; uint16_t* dst; size_t j;
        if (i < n_x)            { src = x;  dst = g_xx;  j = i; }
        else if (i < n_x + n_a) { src = Wa; dst = g_wta; j = i - n_x; }
        else                    { src = Wp; dst = g_wtp; j = i - n_x - n_a; }
        float4 v = *(const float4*)(src + j * 4);
        *(uint2*)&dst[j * 4] = make_uint2(pack_h2(v.x, v.y), pack_h2(v.z, v.w));
    }
}

// ---------------------------------------------------------------------------
// mma.sync fp16 GEMM — BMt x 128 block (BMt=128 for QKV, 64 for proj to fix
// wave quantization: proj grid 512->1024 CTAs, tail 42%->13%).
// BK=64, 8 warps (4M x 2N), 3-stage pipeline, 2 CTA/SM.
// A tile [BMt x 64k] (ROWB=144, ldsm); B tile [64k x 128n] K-major from W
// (BROWB=272, ldsm.trans). Numerics identical to transposed-B version.
// ---------------------------------------------------------------------------
#define BK 64
#define NSTG (Kdim / BK)
#define ROWB 144
#define BROWB 272
#define BMAT (64 * BROWB)          // 17408

template<int NN, int BMt>
__device__ __forceinline__ void preload_stage(uint32_t st,
        const uint16_t* __restrict__ As, const uint16_t* __restrict__ Bs,
        int row0, int col0, int kc, int tid)
{
    constexpr int AMAT = BMt * ROWB;
    #pragma unroll
    for (int i = 0; i < BMt / 32; i++) {     // A: BMt rows x 8 chunks
        int idx = tid + i * 256;
        int r = idx >> 3;
        int c = idx & 7;
        cp16(st + (uint32_t)(r * ROWB + c * 16),
             As + (size_t)(row0 + r) * Kdim + kc + c * 8);
    }
    #pragma unroll
    for (int i = 0; i < 4; i++) {            // B: 64 k-rows x 16 chunks (128n)
        int idx = tid + i * 256;
        int r = idx >> 4;
        int c = idx & 15;
        cp16(st + AMAT + (uint32_t)(r * BROWB + c * 16),
             Bs + (size_t)(kc + r) * NN + col0 + c * 8);
    }
}

template<int MODE>
__global__ void __launch_bounds__(256, 2) mma_gemm_kernel(const float* __restrict__ bias,
                                                          float* __restrict__ out)
{
    constexpr int NN  = (MODE == 0) ? NQKV : Cc;
    constexpr int BMt = (MODE == 0) ? 128 : 64;
    constexpr int MTt = BMt / 64;            // 2 or 1 m-frags per warp
    constexpr int AMAT = BMt * ROWB;
    constexpr int STAGE = AMAT + BMAT;

    extern __shared__ char smem[];
    const uint32_t sb = smem_u32(smem);
    const int tid  = threadIdx.x;
    const int wid  = tid >> 5;
    const int lane = tid & 31;
    const int g = lane >> 2;
    const int t = lane & 3;
    const int warpM = wid & 3;
    const int warpN = wid >> 2;
    const int row0 = blockIdx.y * BMt;
    const int col0 = blockIdx.x * 128;

    const uint16_t* As = (MODE == 0) ? g_xx : g_yy;
    const uint16_t* Bs = (MODE == 0) ? g_wta : g_wtp;

    float acc[MTt][8][4];
    #pragma unroll
    for (int mt = 0; mt < MTt; mt++)
        #pragma unroll
        for (int nt = 0; nt < 8; nt++)
            #pragma unroll
            for (int j = 0; j < 4; j++) acc[mt][nt][j] = 0.f;

    const uint32_t aRowIdx = (uint32_t)(((lane >> 3) & 1) * 8 + (lane & 7));
    const uint32_t aColOff = (uint32_t)(((lane >> 4) & 1) * 16);
    const uint32_t bKRow  = (uint32_t)(((lane >> 3) & 1) * 8 + (lane & 7));
    const uint32_t bNHalf = (uint32_t)(((lane >> 4) & 1) * 16);

    preload_stage<NN, BMt>(sb + 0 * STAGE, As, Bs, row0, col0, 0 * BK, tid); CP_COMMIT();
    preload_stage<NN, BMt>(sb + 1 * STAGE, As, Bs, row0, col0, 1 * BK, tid); CP_COMMIT();

    for (int s = 0; s < NSTG; s++) {
        if (s + 1 < NSTG) { CP_WAIT(1); } else { CP_WAIT(0); }
        __syncthreads();
        if (s + 2 < NSTG) {
            preload_stage<NN, BMt>(sb + (uint32_t)(((s + 2) % 3) * STAGE),
                                   As, Bs, row0, col0, (s + 2) * BK, tid);
            CP_COMMIT();
        }

        const uint32_t stg = sb + (uint32_t)((s % 3) * STAGE);
        const uint32_t Am = stg;
        const uint32_t Bm = stg + AMAT;

        #pragma unroll
        for (int ks = 0; ks < 4; ks++) {
            uint32_t ah[MTt][4];
            #pragma unroll
            for (int mt = 0; mt < MTt; mt++) {
                uint32_t ra = (uint32_t)(warpM * (16 * MTt) + mt * 16) + aRowIdx;
                ldsm_x4(ah[mt], Am + ra * ROWB + (uint32_t)(ks * 32) + aColOff);
            }
            #pragma unroll
            for (int ntp = 0; ntp < 4; ntp++) {
                uint32_t addr = Bm + ((uint32_t)(ks * 16) + bKRow) * BROWB
                              + (uint32_t)(warpN * 128 + ntp * 32) + bNHalf;
                uint32_t bb[4];
                ldsm_x4_t(bb, addr);
                #pragma unroll
                for (int half = 0; half < 2; half++)
                    #pragma unroll
                    for (int mt = 0; mt < MTt; mt++)
                        mma16816(acc[mt][ntp * 2 + half], ah[mt], bb + half * 2);
            }
        }
    }

    #pragma unroll
    for (int mt = 0; mt < MTt; mt++) {
        #pragma unroll
        for (int nt = 0; nt < 8; nt++) {
            #pragma unroll
            for (int half = 0; half < 2; half++) {
                int m = row0 + warpM * (16 * MTt) + mt * 16 + g + half * 8;
                int n = col0 + warpN * 64 + nt * 8 + t * 2;
                float v0 = acc[mt][nt][half * 2 + 0] + bias[n];
                float v1 = acc[mt][nt][half * 2 + 1] + bias[n + 1];
                if (MODE == 0) {
                    int b_ = m >> 11;
                    int tt = m & 2047;
                    int which = n >> 10;
                    int cc = n & 1023;
                    int h = cc >> 6;
                    int d = cc & 63;
                    size_t base = (((size_t)b_ * Hh + h) * Tt + tt) * Dd + d;
                    if (which == 0) {
                        *(uint32_t*)&g_qq[base] = pack_h2(v0 * 0.125f, v1 * 0.125f);
                    } else if (which == 1) {
                        *(uint32_t*)&g_kk[base] = pack_h2(v0, v1);
                    } else {
                        *(uint32_t*)&g_vv[base] = pack_h2(v0, v1);
                    }
                } else {
                    float* p = out + (size_t)m * Cc + n;
                    p[0] = v0; p[1] = v1;
                }
            }
        }
    }
}

#define GEMM_SMEM0 (3 * (128 * ROWB + BMAT))   // 107520
#define GEMM_SMEM1 (3 * (64 * ROWB + BMAT))    // 79872

// ---------------------------------------------------------------------------
// Flash attention via mma.sync fp16 — R13 proven core: TK=128, 2-stage.
// grid (Tt/128, Bb*Hh), 256 threads = 8 warps, warp = 16 q-rows x all keys.
// Softmax: lazy guarded max; exp via ex2.approx.f16x2; l via ones-MMA.
// ---------------------------------------------------------------------------
#define TK 128
#define NTILE (Tt / TK)             // 16
#define AROW 144
#define VOFF2 (128 * AROW)
#define STG_B (256 * AROW)          // 36864
#define ATT_SMEM (2 * STG_B)        // 73728

__device__ __forceinline__ void att_load_stage(uint32_t st, size_t seqBase,
                                               int key0, int tid)
{
    #pragma unroll
    for (int j = 0; j < 4; j++) {
        int idx = tid + j * 256;
        int r = idx >> 3, c = idx & 7;
        uint32_t off = (uint32_t)(r * AROW + c * 16);
        size_t gsrc = seqBase + (size_t)(key0 + r) * Dd + c * 8;
        cp16(st + off,         g_kk + gsrc);
        cp16(st + VOFF2 + off, g_vv + gsrc);
    }
}

__global__ void __launch_bounds__(256, 2) attn_mma_kernel()
{
    extern __shared__ char smem[];
    const uint32_t sb = smem_u32(smem);
    const int tid  = threadIdx.x;
    const int w    = tid >> 5;
    const int lane = tid & 31;
    const int g = lane >> 2;
    const int t = lane & 3;
    const int q0 = blockIdx.x * 128;
    const int bh = blockIdx.y;

    const size_t seqBase = (size_t)bh * Tt * Dd;

    const uint32_t aRowIdx = (uint32_t)(((lane >> 3) & 1) * 8 + (lane & 7));
    const uint32_t aColOff = (uint32_t)(((lane >> 4) & 1) * 16);
    const uint32_t bRowIdx = (uint32_t)(((lane >> 4) & 1) * 8 + (lane & 7));
    const uint32_t bColOff = (uint32_t)(((lane >> 3) & 1) * 16);

    // ---- prologue: Q tile -> smem -> fragments ----
    #pragma unroll
    for (int j = 0; j < 4; j++) {
        int idx = tid + j * 256;
        int r = idx >> 3, c = idx & 7;
        size_t gsrc = seqBase + (size_t)(q0 + r) * Dd + c * 8;
        *(uint4*)(smem + r * AROW + c * 16) = *(const uint4*)(g_qq + gsrc);
    }
    __syncthreads();

    uint32_t qh[4][4];
    {
        uint32_t qrow = (uint32_t)(w * 16) + aRowIdx;
        #pragma unroll
        for (int kf = 0; kf < 4; kf++)
            ldsm_x4(qh[kf], sb + qrow * AROW + kf * 32 + aColOff);
    }
    __syncthreads();

    float oacc[8][4];
    #pragma unroll
    for (int nf = 0; nf < 8; nf++)
        #pragma unroll
        for (int j = 0; j < 4; j++) oacc[nf][j] = 0.f;
    float lacc[4] = {0.f, 0.f, 0.f, 0.f};
    float m0 = 0.f, m1 = 0.f;
    float ml0 = 0.f, ml1 = 0.f;
    const uint32_t onesB[2] = {0x3C003C00u, 0x3C003C00u};

    att_load_stage(sb, seqBase, 0, tid);
    CP_COMMIT();

    for (int kt = 0; kt < NTILE; kt++) {
        CP_WAIT(0);
        __syncthreads();
        if (kt + 1 < NTILE) {
            att_load_stage(sb + ((kt + 1) & 1) * STG_B, seqBase, (kt + 1) * TK, tid);
            CP_COMMIT();
        }

        const uint32_t stg0 = sb + (kt & 1) * STG_B;

        #pragma unroll 1
        for (int h2 = 0; h2 < 2; h2++) {
            const uint32_t stgU = stg0 + (uint32_t)(h2 * 64 * AROW);

            // ---- S = Q K^T ----
            float sacc[8][4];
            #pragma unroll
            for (int nf = 0; nf < 8; nf++)
                #pragma unroll
                for (int j = 0; j < 4; j++) sacc[nf][j] = 0.f;

            #pragma unroll
            for (int kf = 0; kf < 4; kf++) {
                uint32_t bf[8][2];
                #pragma unroll
                for (int p = 0; p < 4; p++) {
                    uint32_t r4[4];
                    ldsm_x4(r4, stgU + ((uint32_t)(p * 16) + bRowIdx) * AROW + kf * 32 + bColOff);
                    bf[2*p][0] = r4[0]; bf[2*p][1] = r4[1];
                    bf[2*p+1][0] = r4[2]; bf[2*p+1][1] = r4[3];
                }
                #pragma unroll
                for (int nf = 0; nf < 8; nf++) mma16816(sacc[nf], qh[kf], bf[nf]);
            }

            // ---- guard: per-lane max + warp vote ----
            float rm0 = sacc[0][0], rm1 = sacc[0][2];
            #pragma unroll
            for (int nf = 0; nf < 8; nf++) {
                rm0 = fmaxf(rm0, fmaxf(sacc[nf][0], sacc[nf][1]));
                rm1 = fmaxf(rm1, fmaxf(sacc[nf][2], sacc[nf][3]));
            }

            if (kt == 0 && h2 == 0) {
                rm0 = fmaxf(rm0, __shfl_xor_sync(0xffffffffu, rm0, 1));
                rm0 = fmaxf(rm0, __shfl_xor_sync(0xffffffffu, rm0, 2));
                rm1 = fmaxf(rm1, __shfl_xor_sync(0xffffffffu, rm1, 1));
                rm1 = fmaxf(rm1, __shfl_xor_sync(0xffffffffu, rm1, 2));
                m0 = rm0; m1 = rm1;
                ml0 = m0 * LOG2E; ml1 = m1 * LOG2E;
            } else if (__any_sync(0xffffffffu, (rm0 > m0 + 8.f) || (rm1 > m1 + 8.f))) {
                rm0 = fmaxf(rm0, __shfl_xor_sync(0xffffffffu, rm0, 1));
                rm0 = fmaxf(rm0, __shfl_xor_sync(0xffffffffu, rm0, 2));
                rm1 = fmaxf(rm1, __shfl_xor_sync(0xffffffffu, rm1, 1));
                rm1 = fmaxf(rm1, __shfl_xor_sync(0xffffffffu, rm1, 2));
                float mn0 = fmaxf(m0, rm0), mn1 = fmaxf(m1, rm1);
                float al0 = exp2f((m0 - mn0) * LOG2E), al1 = exp2f((m1 - mn1) * LOG2E);
                m0 = mn0; m1 = mn1;
                ml0 = m0 * LOG2E; ml1 = m1 * LOG2E;
                lacc[0] *= al0; lacc[1] *= al0; lacc[2] *= al1; lacc[3] *= al1;
                #pragma unroll
                for (int nf = 0; nf < 8; nf++) {
                    oacc[nf][0] *= al0; oacc[nf][1] *= al0;
                    oacc[nf][2] *= al1; oacc[nf][3] *= al1;
                }
            }

            // ---- P = exp2(s*log2e - ml) on fp16 pipe ----
            uint32_t pa[4][4];
            #pragma unroll
            for (int k2 = 0; k2 < 4; k2++) {
                float a0 = fmaf(sacc[2*k2][0],   LOG2E, -ml0);
                float a1 = fmaf(sacc[2*k2][1],   LOG2E, -ml0);
                float a2 = fmaf(sacc[2*k2][2],   LOG2E, -ml1);
                float a3 = fmaf(sacc[2*k2][3],   LOG2E, -ml1);
                float b0 = fmaf(sacc[2*k2+1][0], LOG2E, -ml0);
                float b1 = fmaf(sacc[2*k2+1][1], LOG2E, -ml0);
                float b2 = fmaf(sacc[2*k2+1][2], LOG2E, -ml1);
                float b3 = fmaf(sacc[2*k2+1][3], LOG2E, -ml1);
                pa[k2][0] = h2exp2_u32(pack_h2(a0, a1));
                pa[k2][1] = h2exp2_u32(pack_h2(a2, a3));
                pa[k2][2] = h2exp2_u32(pack_h2(b0, b1));
                pa[k2][3] = h2exp2_u32(pack_h2(b2, b3));
            }

            // ---- O += P V ; l += P·1 ----
            #pragma unroll
            for (int k2 = 0; k2 < 4; k2++) {
                mma16816(lacc, pa[k2], onesB);
                uint32_t vrow = (uint32_t)(k2 * 16 + ((lane >> 3) & 1) * 8 + (lane & 7));
                uint32_t lhalf = (uint32_t)(((lane >> 4) & 1) * 16);
                #pragma unroll
                for (int np = 0; np < 4; np++) {
                    uint32_t rh[4];
                    ldsm_x4_t(rh, stgU + VOFF2 + vrow * AROW + np * 32 + lhalf);
                    mma16816(oacc[2*np],   pa[k2], rh + 0);
                    mma16816(oacc[2*np+1], pa[k2], rh + 2);
                }
            }
        }
    }

    // ---- epilogue: O/l -> smem -> fp16 y (coalesced) ----
    __syncthreads();
    float* Osm = (float*)smem;
    const float inv0 = 1.f / lacc[0], inv1 = 1.f / lacc[2];
    #pragma unroll
    for (int nf = 0; nf < 8; nf++) {
        int c = nf * 8 + t * 2;
        Osm[(w * 16 + g)     * 72 + c]     = oacc[nf][0] * inv0;
        Osm[(w * 16 + g)     * 72 + c + 1] = oacc[nf][1] * inv0;
        Osm[(w * 16 + 8 + g) * 72 + c]     = oacc[nf][2] * inv1;
        Osm[(w * 16 + 8 + g) * 72 + c + 1] = oacc[nf][3] * inv1;
    }
    __syncthreads();

    {
        int r = tid >> 1, half = tid & 1;
        int b_ = bh >> 4, h = bh & 15;
        size_t base = ((size_t)b_ * Tt + q0 + r) * Cc + h * 64 + half * 32;
        uint16_t hb[32];
        #pragma unroll
        for (int i = 0; i < 32; i++)
            hb[i] = to_h(Osm[r * 72 + half * 32 + i]);
        #pragma unroll
        for (int c4 = 0; c4 < 4; c4++)
            *(uint4*)(g_yy + base + c4 * 8) = *(uint4*)(hb + c4 * 8);
    }
}

// ---------------------------------------------------------------------------
extern "C" void kernel_launch(void* const* d_in, const int* in_sizes, int n_in,
                              void* d_out, int out_size)
{
    const float* x      = (const float*)d_in[0];
    const float* W_attn = (const float*)d_in[1];
    const float* b_attn = (const float*)d_in[2];
    const float* W_proj = (const float*)d_in[3];
    const float* b_proj = (const float*)d_in[4];
    float* out = (float*)d_out;

    cudaFuncSetAttribute(mma_gemm_kernel<0>, cudaFuncAttributeMaxDynamicSharedMemorySize, GEMM_SMEM0);
    cudaFuncSetAttribute(mma_gemm_kernel<1>, cudaFuncAttributeMaxDynamicSharedMemorySize, GEMM_SMEM1);
    cudaFuncSetAttribute(attn_mma_kernel, cudaFuncAttributeMaxDynamicSharedMemorySize, ATT_SMEM);

    prep_kernel<<<4096, 256>>>(x, W_attn, W_proj);

    mma_gemm_kernel<0><<<dim3(NQKV / 128, Mrows / 128), 256, GEMM_SMEM0>>>(b_attn, nullptr);

    attn_mma_kernel<<<dim3(Tt / 128, Bb * Hh), 256, ATT_SMEM>>>();

    // proj: BM=64 tiles -> grid 1024 CTAs (3.46 waves, tail 13% vs 42%)
    mma_gemm_kernel<1><<<dim3(Cc / 128, Mrows / 64), 256, GEMM_SMEM1>>>(b_proj, out);
}

// round 16
// speedup vs baseline: 1.0319x; 1.0319x over previous
#include <cuda_runtime.h>
#include <cuda_fp16.h>
#include <cstdint>

#define Bb 4
#define Tt 2048
#define Cc 1024
#define Hh 16
#define Dd 64
#define Kdim 1024
#define NQKV 3072
#define Mrows 8192
#define LOG2E 1.4426950408889634f

// ---------------------------------------------------------------------------
// scratch (__device__ globals; allocation-free). All fp16 (stored as u16).
// g_wta/g_wtp hold NON-transposed fp16 weights [Kdim][N] (K-major rows).
// ---------------------------------------------------------------------------
__device__ uint16_t g_xx[(size_t)Mrows*Kdim];
__device__ uint16_t g_yy[(size_t)Mrows*Kdim];
__device__ uint16_t g_wta[(size_t)Kdim*NQKV];
__device__ uint16_t g_wtp[(size_t)Kdim*Cc];

// attention operands, [b,h,t,d] fp16 (q pre-scaled by 1/8)
__device__ uint16_t g_qq[(size_t)Bb*Hh*Tt*Dd];
__device__ uint16_t g_kk[(size_t)Bb*Hh*Tt*Dd];
__device__ uint16_t g_vv[(size_t)Bb*Hh*Tt*Dd];

// ---------------------------------------------------------------------------
// helpers
// ---------------------------------------------------------------------------
__device__ __forceinline__ uint32_t smem_u32(const void* p) {
    uint32_t a;
    asm("{ .reg .u64 t; cvta.to.shared.u64 t, %1; cvt.u32.u64 %0, t; }" : "=r"(a) : "l"(p));
    return a;
}
__device__ __forceinline__ void cp16(uint32_t dst, const void* src) {
    asm volatile("cp.async.cg.shared.global [%0], [%1], 16;" :: "r"(dst), "l"(src));
}
#define CP_COMMIT() asm volatile("cp.async.commit_group;" ::: "memory")
#define CP_WAIT(n)  asm volatile("cp.async.wait_group %0;" :: "n"(n) : "memory")

__device__ __forceinline__ void mma16816(float d[4], const uint32_t a[4], const uint32_t b[2]) {
    asm volatile(
        "mma.sync.aligned.m16n8k16.row.col.f32.f16.f16.f32 "
        "{%0,%1,%2,%3}, {%4,%5,%6,%7}, {%8,%9}, {%0,%1,%2,%3};"
        : "+f"(d[0]), "+f"(d[1]), "+f"(d[2]), "+f"(d[3])
        : "r"(a[0]), "r"(a[1]), "r"(a[2]), "r"(a[3]), "r"(b[0]), "r"(b[1]));
}
__device__ __forceinline__ void ldsm_x4(uint32_t r[4], uint32_t a) {
    asm volatile("ldmatrix.sync.aligned.m8n8.x4.shared.b16 {%0,%1,%2,%3}, [%4];"
        : "=r"(r[0]), "=r"(r[1]), "=r"(r[2]), "=r"(r[3]) : "r"(a));
}
__device__ __forceinline__ void ldsm_x4_t(uint32_t r[4], uint32_t a) {
    asm volatile("ldmatrix.sync.aligned.m8n8.x4.trans.shared.b16 {%0,%1,%2,%3}, [%4];"
        : "=r"(r[0]), "=r"(r[1]), "=r"(r[2]), "=r"(r[3]) : "r"(a));
}

__device__ __forceinline__ uint16_t to_h(float v) {
    __half hb = __float2half_rn(v);
    return *reinterpret_cast<uint16_t*>(&hb);
}
__device__ __forceinline__ uint32_t pack_h2(float a, float b) {
    __half2 h2 = __floats2half2_rn(a, b);
    return *reinterpret_cast<uint32_t*>(&h2);
}
__device__ __forceinline__ uint32_t h2exp2_u32(uint32_t x) {
    __half2 h = *reinterpret_cast<__half2*>(&x);
    __half2 r = h2exp2(h);
    return *reinterpret_cast<uint32_t*>(&r);
}

// ---------------------------------------------------------------------------
// prep: ONE pure fp32->fp16 convert pass over x, W_attn, W_proj.
// ---------------------------------------------------------------------------
__global__ void prep_kernel(const float* __restrict__ x,
                            const float* __restrict__ Wa,
                            const float* __restrict__ Wp)
{
    const size_t n_x = (size_t)Mrows * Kdim / 4;
    const size_t n_a = (size_t)Kdim * NQKV / 4;
    const size_t n_p = (size_t)Kdim * Cc / 4;
    const size_t tot = n_x + n_a + n_p;
    for (size_t i = blockIdx.x * (size_t)blockDim.x + threadIdx.x; i < tot;
         i += (size_t)gridDim.x * blockDim.x) {
        const float* src; uint16_t* dst; size_t j;
        if (i < n_x)            { src = x;  dst = g_xx;  j = i; }
        else if (i < n_x + n_a) { src = Wa; dst = g_wta; j = i - n_x; }
        else                    { src = Wp; dst = g_wtp; j = i - n_x - n_a; }
        float4 v = *(const float4*)(src + j * 4);
        *(uint2*)&dst[j * 4] = make_uint2(pack_h2(v.x, v.y), pack_h2(v.z, v.w));
    }
}

// ---------------------------------------------------------------------------
// mma.sync fp16 GEMM — 128x128 block for BOTH modes (BM=64 proj regressed:
// thinner per-CTA work loses more than wave smoothing gains — R10, R15).
// BK=64, 8 warps (4M x 2N), 3-stage pipeline, 2 CTA/SM.
// A tile [128 x 64k] (ROWB=144, ldsm); B tile [64k x 128n] K-major from W
// (BROWB=272, ldsm.trans). Numerics identical to transposed-B version.
// ---------------------------------------------------------------------------
#define BK 64
#define NSTG (Kdim / BK)
#define ROWB 144
#define BROWB 272
#define AMAT (128 * ROWB)          // 18432
#define BMAT (64 * BROWB)          // 17408
#define STAGE_B (AMAT + BMAT)      // 35840
#define GEMM_SMEM (3 * STAGE_B)    // 107520

template<int NN>
__device__ __forceinline__ void preload_stage(uint32_t st,
        const uint16_t* __restrict__ As, const uint16_t* __restrict__ Bs,
        int row0, int col0, int kc, int tid)
{
    #pragma unroll
    for (int i = 0; i < 4; i++) {            // A: 128 rows x 8 chunks
        int idx = tid + i * 256;
        int r = idx >> 3;
        int c = idx & 7;
        cp16(st + (uint32_t)(r * ROWB + c * 16),
             As + (size_t)(row0 + r) * Kdim + kc + c * 8);
    }
    #pragma unroll
    for (int i = 0; i < 4; i++) {            // B: 64 k-rows x 16 chunks (128n)
        int idx = tid + i * 256;
        int r = idx >> 4;
        int c = idx & 15;
        cp16(st + AMAT + (uint32_t)(r * BROWB + c * 16),
             Bs + (size_t)(kc + r) * NN + col0 + c * 8);
    }
}

template<int MODE>
__global__ void __launch_bounds__(256, 2) mma_gemm_kernel(const float* __restrict__ bias,
                                                          float* __restrict__ out)
{
    constexpr int NN = (MODE == 0) ? NQKV : Cc;
    extern __shared__ char smem[];
    const uint32_t sb = smem_u32(smem);
    const int tid  = threadIdx.x;
    const int wid  = tid >> 5;
    const int lane = tid & 31;
    const int g = lane >> 2;
    const int t = lane & 3;
    const int warpM = wid & 3;
    const int warpN = wid >> 2;
    const int row0 = blockIdx.y * 128;
    const int col0 = blockIdx.x * 128;

    const uint16_t* As = (MODE == 0) ? g_xx : g_yy;
    const uint16_t* Bs = (MODE == 0) ? g_wta : g_wtp;

    float acc[2][8][4];
    #pragma unroll
    for (int mt = 0; mt < 2; mt++)
        #pragma unroll
        for (int nt = 0; nt < 8; nt++)
            #pragma unroll
            for (int j = 0; j < 4; j++) acc[mt][nt][j] = 0.f;

    const uint32_t aRowIdx = (uint32_t)(((lane >> 3) & 1) * 8 + (lane & 7));
    const uint32_t aColOff = (uint32_t)(((lane >> 4) & 1) * 16);
    const uint32_t bKRow  = (uint32_t)(((lane >> 3) & 1) * 8 + (lane & 7));
    const uint32_t bNHalf = (uint32_t)(((lane >> 4) & 1) * 16);

    preload_stage<NN>(sb + 0 * STAGE_B, As, Bs, row0, col0, 0 * BK, tid); CP_COMMIT();
    preload_stage<NN>(sb + 1 * STAGE_B, As, Bs, row0, col0, 1 * BK, tid); CP_COMMIT();

    for (int s = 0; s < NSTG; s++) {
        if (s + 1 < NSTG) { CP_WAIT(1); } else { CP_WAIT(0); }
        __syncthreads();
        if (s + 2 < NSTG) {
            preload_stage<NN>(sb + (uint32_t)(((s + 2) % 3) * STAGE_B),
                              As, Bs, row0, col0, (s + 2) * BK, tid);
            CP_COMMIT();
        }

        const uint32_t stg = sb + (uint32_t)((s % 3) * STAGE_B);
        const uint32_t Am = stg;
        const uint32_t Bm = stg + AMAT;

        #pragma unroll
        for (int ks = 0; ks < 4; ks++) {
            uint32_t ah[2][4];
            #pragma unroll
            for (int mt = 0; mt < 2; mt++) {
                uint32_t ra = (uint32_t)(warpM * 32 + mt * 16) + aRowIdx;
                ldsm_x4(ah[mt], Am + ra * ROWB + (uint32_t)(ks * 32) + aColOff);
            }
            #pragma unroll
            for (int ntp = 0; ntp < 4; ntp++) {
                uint32_t addr = Bm + ((uint32_t)(ks * 16) + bKRow) * BROWB
                              + (uint32_t)(warpN * 128 + ntp * 32) + bNHalf;
                uint32_t bb[4];
                ldsm_x4_t(bb, addr);
                #pragma unroll
                for (int half = 0; half < 2; half++)
                    #pragma unroll
                    for (int mt = 0; mt < 2; mt++)
                        mma16816(acc[mt][ntp * 2 + half], ah[mt], bb + half * 2);
            }
        }
    }

    #pragma unroll
    for (int mt = 0; mt < 2; mt++) {
        #pragma unroll
        for (int nt = 0; nt < 8; nt++) {
            #pragma unroll
            for (int half = 0; half < 2; half++) {
                int m = row0 + warpM * 32 + mt * 16 + g + half * 8;
                int n = col0 + warpN * 64 + nt * 8 + t * 2;
                float v0 = acc[mt][nt][half * 2 + 0] + bias[n];
                float v1 = acc[mt][nt][half * 2 + 1] + bias[n + 1];
                if (MODE == 0) {
                    int b_ = m >> 11;
                    int tt = m & 2047;
                    int which = n >> 10;
                    int cc = n & 1023;
                    int h = cc >> 6;
                    int d = cc & 63;
                    size_t base = (((size_t)b_ * Hh + h) * Tt + tt) * Dd + d;
                    if (which == 0) {
                        *(uint32_t*)&g_qq[base] = pack_h2(v0 * 0.125f, v1 * 0.125f);
                    } else if (which == 1) {
                        *(uint32_t*)&g_kk[base] = pack_h2(v0, v1);
                    } else {
                        *(uint32_t*)&g_vv[base] = pack_h2(v0, v1);
                    }
                } else {
                    float* p = out + (size_t)m * Cc + n;
                    p[0] = v0; p[1] = v1;
                }
            }
        }
    }
}

// ---------------------------------------------------------------------------
// Flash attention via mma.sync fp16 — proven core: TK=128, 2-stage.
// grid (Tt/128, Bb*Hh), 256 threads = 8 warps, warp = 16 q-rows x all keys.
// Softmax: lazy guarded max; exp via ex2.approx.f16x2; l via ones-MMA.
// ---------------------------------------------------------------------------
#define TK 128
#define NTILE (Tt / TK)             // 16
#define AROW 144
#define VOFF2 (128 * AROW)
#define STG_B (256 * AROW)          // 36864
#define ATT_SMEM (2 * STG_B)        // 73728

__device__ __forceinline__ void att_load_stage(uint32_t st, size_t seqBase,
                                               int key0, int tid)
{
    #pragma unroll
    for (int j = 0; j < 4; j++) {
        int idx = tid + j * 256;
        int r = idx >> 3, c = idx & 7;
        uint32_t off = (uint32_t)(r * AROW + c * 16);
        size_t gsrc = seqBase + (size_t)(key0 + r) * Dd + c * 8;
        cp16(st + off,         g_kk + gsrc);
        cp16(st + VOFF2 + off, g_vv + gsrc);
    }
}

__global__ void __launch_bounds__(256, 2) attn_mma_kernel()
{
    extern __shared__ char smem[];
    const uint32_t sb = smem_u32(smem);
    const int tid  = threadIdx.x;
    const int w    = tid >> 5;
    const int lane = tid & 31;
    const int g = lane >> 2;
    const int t = lane & 3;
    const int q0 = blockIdx.x * 128;
    const int bh = blockIdx.y;

    const size_t seqBase = (size_t)bh * Tt * Dd;

    const uint32_t aRowIdx = (uint32_t)(((lane >> 3) & 1) * 8 + (lane & 7));
    const uint32_t aColOff = (uint32_t)(((lane >> 4) & 1) * 16);
    const uint32_t bRowIdx = (uint32_t)(((lane >> 4) & 1) * 8 + (lane & 7));
    const uint32_t bColOff = (uint32_t)(((lane >> 3) & 1) * 16);

    // ---- prologue: Q tile -> smem -> fragments ----
    #pragma unroll
    for (int j = 0; j < 4; j++) {
        int idx = tid + j * 256;
        int r = idx >> 3, c = idx & 7;
        size_t gsrc = seqBase + (size_t)(q0 + r) * Dd + c * 8;
        *(uint4*)(smem + r * AROW + c * 16) = *(const uint4*)(g_qq + gsrc);
    }
    __syncthreads();

    uint32_t qh[4][4];
    {
        uint32_t qrow = (uint32_t)(w * 16) + aRowIdx;
        #pragma unroll
        for (int kf = 0; kf < 4; kf++)
            ldsm_x4(qh[kf], sb + qrow * AROW + kf * 32 + aColOff);
    }
    __syncthreads();

    float oacc[8][4];
    #pragma unroll
    for (int nf = 0; nf < 8; nf++)
        #pragma unroll
        for (int j = 0; j < 4; j++) oacc[nf][j] = 0.f;
    float lacc[4] = {0.f, 0.f, 0.f, 0.f};
    float m0 = 0.f, m1 = 0.f;
    float ml0 = 0.f, ml1 = 0.f;
    const uint32_t onesB[2] = {0x3C003C00u, 0x3C003C00u};

    att_load_stage(sb, seqBase, 0, tid);
    CP_COMMIT();

    for (int kt = 0; kt < NTILE; kt++) {
        CP_WAIT(0);
        __syncthreads();
        if (kt + 1 < NTILE) {
            att_load_stage(sb + ((kt + 1) & 1) * STG_B, seqBase, (kt + 1) * TK, tid);
            CP_COMMIT();
        }

        const uint32_t stg0 = sb + (kt & 1) * STG_B;

        #pragma unroll 1
        for (int h2 = 0; h2 < 2; h2++) {
            const uint32_t stgU = stg0 + (uint32_t)(h2 * 64 * AROW);

            // ---- S = Q K^T ----
            float sacc[8][4];
            #pragma unroll
            for (int nf = 0; nf < 8; nf++)
                #pragma unroll
                for (int j = 0; j < 4; j++) sacc[nf][j] = 0.f;

            #pragma unroll
            for (int kf = 0; kf < 4; kf++) {
                uint32_t bf[8][2];
                #pragma unroll
                for (int p = 0; p < 4; p++) {
                    uint32_t r4[4];
                    ldsm_x4(r4, stgU + ((uint32_t)(p * 16) + bRowIdx) * AROW + kf * 32 + bColOff);
                    bf[2*p][0] = r4[0]; bf[2*p][1] = r4[1];
                    bf[2*p+1][0] = r4[2]; bf[2*p+1][1] = r4[3];
                }
                #pragma unroll
                for (int nf = 0; nf < 8; nf++) mma16816(sacc[nf], qh[kf], bf[nf]);
            }

            // ---- guard: per-lane max + warp vote ----
            float rm0 = sacc[0][0], rm1 = sacc[0][2];
            #pragma unroll
            for (int nf = 0; nf < 8; nf++) {
                rm0 = fmaxf(rm0, fmaxf(sacc[nf][0], sacc[nf][1]));
                rm1 = fmaxf(rm1, fmaxf(sacc[nf][2], sacc[nf][3]));
            }

            if (kt == 0 && h2 == 0) {
                rm0 = fmaxf(rm0, __shfl_xor_sync(0xffffffffu, rm0, 1));
                rm0 = fmaxf(rm0, __shfl_xor_sync(0xffffffffu, rm0, 2));
                rm1 = fmaxf(rm1, __shfl_xor_sync(0xffffffffu, rm1, 1));
                rm1 = fmaxf(rm1, __shfl_xor_sync(0xffffffffu, rm1, 2));
                m0 = rm0; m1 = rm1;
                ml0 = m0 * LOG2E; ml1 = m1 * LOG2E;
            } else if (__any_sync(0xffffffffu, (rm0 > m0 + 8.f) || (rm1 > m1 + 8.f))) {
                rm0 = fmaxf(rm0, __shfl_xor_sync(0xffffffffu, rm0, 1));
                rm0 = fmaxf(rm0, __shfl_xor_sync(0xffffffffu, rm0, 2));
                rm1 = fmaxf(rm1, __shfl_xor_sync(0xffffffffu, rm1, 1));
                rm1 = fmaxf(rm1, __shfl_xor_sync(0xffffffffu, rm1, 2));
                float mn0 = fmaxf(m0, rm0), mn1 = fmaxf(m1, rm1);
                float al0 = exp2f((m0 - mn0) * LOG2E), al1 = exp2f((m1 - mn1) * LOG2E);
                m0 = mn0; m1 = mn1;
                ml0 = m0 * LOG2E; ml1 = m1 * LOG2E;
                lacc[0] *= al0; lacc[1] *= al0; lacc[2] *= al1; lacc[3] *= al1;
                #pragma unroll
                for (int nf = 0; nf < 8; nf++) {
                    oacc[nf][0] *= al0; oacc[nf][1] *= al0;
                    oacc[nf][2] *= al1; oacc[nf][3] *= al1;
                }
            }

            // ---- P = exp2(s*log2e - ml) on fp16 pipe ----
            uint32_t pa[4][4];
            #pragma unroll
            for (int k2 = 0; k2 < 4; k2++) {
                float a0 = fmaf(sacc[2*k2][0],   LOG2E, -ml0);
                float a1 = fmaf(sacc[2*k2][1],   LOG2E, -ml0);
                float a2 = fmaf(sacc[2*k2][2],   LOG2E, -ml1);
                float a3 = fmaf(sacc[2*k2][3],   LOG2E, -ml1);
                float b0 = fmaf(sacc[2*k2+1][0], LOG2E, -ml0);
                float b1 = fmaf(sacc[2*k2+1][1], LOG2E, -ml0);
                float b2 = fmaf(sacc[2*k2+1][2], LOG2E, -ml1);
                float b3 = fmaf(sacc[2*k2+1][3], LOG2E, -ml1);
                pa[k2][0] = h2exp2_u32(pack_h2(a0, a1));
                pa[k2][1] = h2exp2_u32(pack_h2(a2, a3));
                pa[k2][2] = h2exp2_u32(pack_h2(b0, b1));
                pa[k2][3] = h2exp2_u32(pack_h2(b2, b3));
            }

            // ---- O += P V ; l += P·1 ----
            #pragma unroll
            for (int k2 = 0; k2 < 4; k2++) {
                mma16816(lacc, pa[k2], onesB);
                uint32_t vrow = (uint32_t)(k2 * 16 + ((lane >> 3) & 1) * 8 + (lane & 7));
                uint32_t lhalf = (uint32_t)(((lane >> 4) & 1) * 16);
                #pragma unroll
                for (int np = 0; np < 4; np++) {
                    uint32_t rh[4];
                    ldsm_x4_t(rh, stgU + VOFF2 + vrow * AROW + np * 32 + lhalf);
                    mma16816(oacc[2*np],   pa[k2], rh + 0);
                    mma16816(oacc[2*np+1], pa[k2], rh + 2);
                }
            }
        }
    }

    // ---- epilogue: O/l -> smem -> fp16 y (coalesced) ----
    __syncthreads();
    float* Osm = (float*)smem;
    const float inv0 = 1.f / lacc[0], inv1 = 1.f / lacc[2];
    #pragma unroll
    for (int nf = 0; nf < 8; nf++) {
        int c = nf * 8 + t * 2;
        Osm[(w * 16 + g)     * 72 + c]     = oacc[nf][0] * inv0;
        Osm[(w * 16 + g)     * 72 + c + 1] = oacc[nf][1] * inv0;
        Osm[(w * 16 + 8 + g) * 72 + c]     = oacc[nf][2] * inv1;
        Osm[(w * 16 + 8 + g) * 72 + c + 1] = oacc[nf][3] * inv1;
    }
    __syncthreads();

    {
        int r = tid >> 1, half = tid & 1;
        int b_ = bh >> 4, h = bh & 15;
        size_t base = ((size_t)b_ * Tt + q0 + r) * Cc + h * 64 + half * 32;
        uint16_t hb[32];
        #pragma unroll
        for (int i = 0; i < 32; i++)
            hb[i] = to_h(Osm[r * 72 + half * 32 + i]);
        #pragma unroll
        for (int c4 = 0; c4 < 4; c4++)
            *(uint4*)(g_yy + base + c4 * 8) = *(uint4*)(hb + c4 * 8);
    }
}

// ---------------------------------------------------------------------------
extern "C" void kernel_launch(void* const* d_in, const int* in_sizes, int n_in,
                              void* d_out, int out_size)
{
    const float* x      = (const float*)d_in[0];
    const float* W_attn = (const float*)d_in[1];
    const float* b_attn = (const float*)d_in[2];
    const float* W_proj = (const float*)d_in[3];
    const float* b_proj = (const float*)d_in[4];
    float* out = (float*)d_out;

    cudaFuncSetAttribute(mma_gemm_kernel<0>, cudaFuncAttributeMaxDynamicSharedMemorySize, GEMM_SMEM);
    cudaFuncSetAttribute(mma_gemm_kernel<1>, cudaFuncAttributeMaxDynamicSharedMemorySize, GEMM_SMEM);
    cudaFuncSetAttribute(attn_mma_kernel, cudaFuncAttributeMaxDynamicSharedMemorySize, ATT_SMEM);

    prep_kernel<<<4096, 256>>>(x, W_attn, W_proj);

    mma_gemm_kernel<0><<<dim3(NQKV / 128, Mrows / 128), 256, GEMM_SMEM>>>(b_attn, nullptr);

    attn_mma_kernel<<<dim3(Tt / 128, Bb * Hh), 256, ATT_SMEM>>>();

    mma_gemm_kernel<1><<<dim3(Cc / 128, Mrows / 128), 256, GEMM_SMEM>>>(b_proj, out);
}